// round 2
// baseline (speedup 1.0000x reference)
#include <cuda_runtime.h>
#include <math.h>

#define BDIM 1024
#define SEQ  2048
#define NH   16
#define DKH  64
#define HIDN 4096
#define MROWS 4096   // B*S
#define NB   2

// ---------------- scratch (static device globals; no allocation) ----------------
__device__ float g_Q  [MROWS * BDIM];
__device__ float g_K  [MROWS * BDIM];
__device__ float g_V  [MROWS * BDIM];
__device__ float g_att[MROWS * BDIM];
__device__ float g_s1 [MROWS * BDIM];
__device__ float g_x1 [MROWS * BDIM];
__device__ float g_hid[MROWS * HIDN];
__device__ float g_s2 [MROWS * BDIM];

enum { MODE_PLAIN = 0, MODE_RELU = 1, MODE_RES = 2, MODE_SPLIT = 3 };

// ---------------- SGEMM: C[M,N] = A[M,K] @ B[K,N] + bias (+epilogue) ----------------
// 128x128 tile, BK=8, 256 threads, 8x8 per thread (two 4-wide halves).
__global__ __launch_bounds__(256, 2) void sgemm_kernel(
    const float* __restrict__ A, const float* __restrict__ B,
    const float* __restrict__ bias, const float* __restrict__ R,
    float* __restrict__ C, int M, int N, int K, int mode)
{
    __shared__ float As[8][128];
    __shared__ float Bs[8][128];

    const int tid  = threadIdx.x;
    const int tx   = tid & 15;
    const int ty   = tid >> 4;
    const int row0 = blockIdx.y * 128;
    const int col0 = blockIdx.x * 128;

    const int aRow = tid >> 1;
    const int aCol = (tid & 1) * 4;
    const int bRow = tid >> 5;
    const int bCol = (tid & 31) * 4;

    const float* Ag = A + (size_t)(row0 + aRow) * K + aCol;
    const float* Bg = B + (size_t)bRow * N + col0 + bCol;

    float acc[8][8];
#pragma unroll
    for (int i = 0; i < 8; i++)
#pragma unroll
        for (int j = 0; j < 8; j++) acc[i][j] = 0.f;

    for (int k0 = 0; k0 < K; k0 += 8) {
        float4 av = *(const float4*)(Ag + k0);
        As[aCol + 0][aRow] = av.x;
        As[aCol + 1][aRow] = av.y;
        As[aCol + 2][aRow] = av.z;
        As[aCol + 3][aRow] = av.w;
        *(float4*)&Bs[bRow][bCol] = *(const float4*)(Bg + (size_t)k0 * N);
        __syncthreads();

#pragma unroll
        for (int k = 0; k < 8; k++) {
            float4 a0 = *(const float4*)&As[k][ty * 4];
            float4 a1 = *(const float4*)&As[k][64 + ty * 4];
            float4 b0 = *(const float4*)&Bs[k][tx * 4];
            float4 b1 = *(const float4*)&Bs[k][64 + tx * 4];
            float ra[8] = {a0.x, a0.y, a0.z, a0.w, a1.x, a1.y, a1.z, a1.w};
            float rb[8] = {b0.x, b0.y, b0.z, b0.w, b1.x, b1.y, b1.z, b1.w};
#pragma unroll
            for (int i = 0; i < 8; i++)
#pragma unroll
                for (int j = 0; j < 8; j++)
                    acc[i][j] = fmaf(ra[i], rb[j], acc[i][j]);
        }
        __syncthreads();
    }

    // epilogue
#pragma unroll
    for (int i = 0; i < 8; i++) {
        int m = row0 + ((i < 4) ? (ty * 4 + i) : (64 + ty * 4 + i - 4));
#pragma unroll
        for (int jh = 0; jh < 2; jh++) {
            int n = col0 + ((jh == 0) ? (tx * 4) : (64 + tx * 4));
            float4 v;
            v.x = acc[i][jh * 4 + 0];
            v.y = acc[i][jh * 4 + 1];
            v.z = acc[i][jh * 4 + 2];
            v.w = acc[i][jh * 4 + 3];
            float4 bz = *(const float4*)&bias[n];
            v.x += bz.x; v.y += bz.y; v.z += bz.z; v.w += bz.w;
            if (mode == MODE_RELU) {
                v.x = fmaxf(v.x, 0.f); v.y = fmaxf(v.y, 0.f);
                v.z = fmaxf(v.z, 0.f); v.w = fmaxf(v.w, 0.f);
            } else if (mode == MODE_RES) {
                float4 r4 = *(const float4*)&R[(size_t)m * N + n];
                v.x += r4.x; v.y += r4.y; v.z += r4.z; v.w += r4.w;
            }
            if (mode == MODE_SPLIT) {
                int hh = n >> 6, dk = n & 63;
                int bb = m >> 11, s = m & 2047;
                *(float4*)&C[(((size_t)(bb * NH + hh)) * SEQ + s) * DKH + dk] = v;
            } else {
                *(float4*)&C[(size_t)m * N + n] = v;
            }
        }
    }
}

// ---------------- Fused flash attention (fp32) ----------------
// Q,K,V: [B,H,S,DK]. Output written back in [B,S,D] layout.
// CTA: 64 queries x DK=64; 256 threads as 16x16, 4x4 per thread.
#define AST 65

__global__ __launch_bounds__(256) void attn_kernel(
    const float* __restrict__ Q, const float* __restrict__ Kg,
    const float* __restrict__ Vg, const int* __restrict__ mask,
    float* __restrict__ O)
{
    extern __shared__ float sm[];
    float* Qs = sm;
    float* Ks = Qs + 64 * AST;
    float* Vs = Ks + 64 * AST;
    float* Ps = Vs + 64 * AST;
    int*   msk = (int*)(Ps + 64 * AST);

    const int tid = threadIdx.x;
    const int tx  = tid & 15;
    const int ty  = tid >> 4;
    const int q0  = blockIdx.x * 64;
    const int h   = blockIdx.y;
    const int bz  = blockIdx.z;

    const size_t headoff = ((size_t)(bz * NH + h)) * SEQ * DKH;
    const float* Qb = Q  + headoff;
    const float* Kb = Kg + headoff;
    const float* Vb = Vg + headoff;

    {   // load Q tile
        int r  = tid >> 2;
        int d0 = (tid & 3) * 16;
        const float* src = Qb + (size_t)(q0 + r) * DKH + d0;
#pragma unroll
        for (int u = 0; u < 4; u++) {
            float4 v4 = *(const float4*)(src + u * 4);
            float* dst = &Qs[r * AST + d0 + u * 4];
            dst[0] = v4.x; dst[1] = v4.y; dst[2] = v4.z; dst[3] = v4.w;
        }
    }

    float mrow[4], lrow[4], o[4][4];
#pragma unroll
    for (int i = 0; i < 4; i++) {
        mrow[i] = -INFINITY; lrow[i] = 0.f;
#pragma unroll
        for (int j = 0; j < 4; j++) o[i][j] = 0.f;
    }

    for (int kv0 = 0; kv0 < SEQ; kv0 += 64) {
        __syncthreads();
        {   // load K/V tiles + mask
            int r  = tid >> 2;
            int d0 = (tid & 3) * 16;
            const float* ks = Kb + (size_t)(kv0 + r) * DKH + d0;
            const float* vg = Vb + (size_t)(kv0 + r) * DKH + d0;
#pragma unroll
            for (int u = 0; u < 4; u++) {
                float4 k4 = *(const float4*)(ks + u * 4);
                float* kd = &Ks[r * AST + d0 + u * 4];
                kd[0] = k4.x; kd[1] = k4.y; kd[2] = k4.z; kd[3] = k4.w;
                float4 v4 = *(const float4*)(vg + u * 4);
                float* vd = &Vs[r * AST + d0 + u * 4];
                vd[0] = v4.x; vd[1] = v4.y; vd[2] = v4.z; vd[3] = v4.w;
            }
            if (tid < 64) msk[tid] = mask[bz * SEQ + kv0 + tid];
        }
        __syncthreads();

        // scores S = Q @ K^T
        float s[4][4];
#pragma unroll
        for (int i = 0; i < 4; i++)
#pragma unroll
            for (int j = 0; j < 4; j++) s[i][j] = 0.f;

        const float* qb0 = &Qs[(ty * 4) * AST];
        const float* kb0 = &Ks[(tx * 4) * AST];
#pragma unroll 8
        for (int k = 0; k < 64; k++) {
            float qv[4], kv[4];
            qv[0] = qb0[k];           qv[1] = qb0[AST + k];
            qv[2] = qb0[2 * AST + k]; qv[3] = qb0[3 * AST + k];
            kv[0] = kb0[k];           kv[1] = kb0[AST + k];
            kv[2] = kb0[2 * AST + k]; kv[3] = kb0[3 * AST + k];
#pragma unroll
            for (int i = 0; i < 4; i++)
#pragma unroll
                for (int j = 0; j < 4; j++)
                    s[i][j] = fmaf(qv[i], kv[j], s[i][j]);
        }

        // scale + mask
#pragma unroll
        for (int j = 0; j < 4; j++) {
            bool mz = (msk[tx * 4 + j] == 0);
#pragma unroll
            for (int i = 0; i < 4; i++)
                s[i][j] = mz ? -1e9f : s[i][j] * 0.125f;
        }

        // online softmax
#pragma unroll
        for (int i = 0; i < 4; i++) {
            float rm = fmaxf(fmaxf(s[i][0], s[i][1]), fmaxf(s[i][2], s[i][3]));
#pragma unroll
            for (int off = 8; off > 0; off >>= 1)
                rm = fmaxf(rm, __shfl_xor_sync(0xffffffffu, rm, off));
            float mn    = fmaxf(mrow[i], rm);
            float alpha = __expf(mrow[i] - mn);
            float rs    = 0.f;
#pragma unroll
            for (int j = 0; j < 4; j++) {
                float p = __expf(s[i][j] - mn);
                s[i][j] = p;
                rs += p;
            }
#pragma unroll
            for (int off = 8; off > 0; off >>= 1)
                rs += __shfl_xor_sync(0xffffffffu, rs, off);
            lrow[i] = lrow[i] * alpha + rs;
            mrow[i] = mn;
#pragma unroll
            for (int j = 0; j < 4; j++) o[i][j] *= alpha;
        }

        // stage P
#pragma unroll
        for (int i = 0; i < 4; i++)
#pragma unroll
            for (int j = 0; j < 4; j++)
                Ps[(ty * 4 + i) * AST + tx * 4 + j] = s[i][j];
        __syncwarp();

        // O += P @ V
        const float* pb0 = &Ps[(ty * 4) * AST];
        const float* vb0 = &Vs[tx * 4];
#pragma unroll 8
        for (int kk = 0; kk < 64; kk++) {
            float pv[4], vv[4];
            pv[0] = pb0[kk];           pv[1] = pb0[AST + kk];
            pv[2] = pb0[2 * AST + kk]; pv[3] = pb0[3 * AST + kk];
            vv[0] = vb0[kk * AST + 0]; vv[1] = vb0[kk * AST + 1];
            vv[2] = vb0[kk * AST + 2]; vv[3] = vb0[kk * AST + 3];
#pragma unroll
            for (int i = 0; i < 4; i++)
#pragma unroll
                for (int j = 0; j < 4; j++)
                    o[i][j] = fmaf(pv[i], vv[j], o[i][j]);
        }
    }

    // epilogue: normalize, write to [B,S,D]
#pragma unroll
    for (int i = 0; i < 4; i++) {
        float inv = 1.f / (lrow[i] > 0.f ? lrow[i] : 1.f);
        int m = q0 + ty * 4 + i;
        float4 v4;
        v4.x = o[i][0] * inv; v4.y = o[i][1] * inv;
        v4.z = o[i][2] * inv; v4.w = o[i][3] * inv;
        *(float4*)&O[((size_t)bz * SEQ + m) * BDIM + h * DKH + tx * 4] = v4;
    }
}

// ---------------- LayerNorm: one CTA per row of 1024 ----------------
__global__ __launch_bounds__(256) void ln_kernel(
    const float* __restrict__ X, const float* __restrict__ g,
    const float* __restrict__ b, float* __restrict__ Y)
{
    __shared__ float red[2][8];
    __shared__ float stats[2];
    const int row = blockIdx.x;
    const int tid = threadIdx.x;

    const float4 v = ((const float4*)(X + (size_t)row * BDIM))[tid];
    float s = v.x + v.y + v.z + v.w;
    float q = v.x * v.x + v.y * v.y + v.z * v.z + v.w * v.w;
#pragma unroll
    for (int o = 16; o > 0; o >>= 1) {
        s += __shfl_xor_sync(0xffffffffu, s, o);
        q += __shfl_xor_sync(0xffffffffu, q, o);
    }
    const int lane = tid & 31, w = tid >> 5;
    if (lane == 0) { red[0][w] = s; red[1][w] = q; }
    __syncthreads();
    if (tid < 32) {
        s = (tid < 8) ? red[0][tid] : 0.f;
        q = (tid < 8) ? red[1][tid] : 0.f;
#pragma unroll
        for (int o = 4; o > 0; o >>= 1) {
            s += __shfl_xor_sync(0xffffffffu, s, o);
            q += __shfl_xor_sync(0xffffffffu, q, o);
        }
        if (tid == 0) {
            float mean = s * (1.f / BDIM);
            stats[0] = mean;
            stats[1] = rsqrtf(q * (1.f / BDIM) - mean * mean + 1e-5f);
        }
    }
    __syncthreads();
    const float mean = stats[0], rinv = stats[1];
    const float4 gg = ((const float4*)g)[tid];
    const float4 bb = ((const float4*)b)[tid];
    float4 o4;
    o4.x = (v.x - mean) * rinv * gg.x + bb.x;
    o4.y = (v.y - mean) * rinv * gg.y + bb.y;
    o4.z = (v.z - mean) * rinv * gg.z + bb.z;
    o4.w = (v.w - mean) * rinv * gg.w + bb.w;
    ((float4*)(Y + (size_t)row * BDIM))[tid] = o4;
}

// ---------------- launcher ----------------
extern "C" void kernel_launch(void* const* d_in, const int* in_sizes, int n_in,
                              void* d_out, int out_size)
{
    const float* x    = (const float*)d_in[0];
    const float* y    = (const float*)d_in[1];
    const int*   mask = (const int*)  d_in[2];
    const float* Wq = (const float*)d_in[3];  const float* bq = (const float*)d_in[4];
    const float* Wk = (const float*)d_in[5];  const float* bk = (const float*)d_in[6];
    const float* Wv = (const float*)d_in[7];  const float* bv = (const float*)d_in[8];
    const float* Wo = (const float*)d_in[9];  const float* bo = (const float*)d_in[10];
    const float* W1 = (const float*)d_in[11]; const float* b1 = (const float*)d_in[12];
    const float* W2 = (const float*)d_in[13]; const float* b2 = (const float*)d_in[14];
    const float* g1 = (const float*)d_in[15]; const float* be1 = (const float*)d_in[16];
    const float* g2 = (const float*)d_in[17]; const float* be2 = (const float*)d_in[18];
    float* out = (float*)d_out;

    float *Qp, *Kp, *Vp, *attp, *s1p, *x1p, *hp, *s2p;
    cudaGetSymbolAddress((void**)&Qp,   g_Q);
    cudaGetSymbolAddress((void**)&Kp,   g_K);
    cudaGetSymbolAddress((void**)&Vp,   g_V);
    cudaGetSymbolAddress((void**)&attp, g_att);
    cudaGetSymbolAddress((void**)&s1p,  g_s1);
    cudaGetSymbolAddress((void**)&x1p,  g_x1);
    cudaGetSymbolAddress((void**)&hp,   g_hid);
    cudaGetSymbolAddress((void**)&s2p,  g_s2);

    dim3 blk(256);
    dim3 gD(BDIM / 128, MROWS / 128);   // (8, 32)
    dim3 gH(HIDN / 128, MROWS / 128);   // (32, 32)

    // QKV projections -> [B,H,S,DK]
    sgemm_kernel<<<gD, blk>>>(x, Wq, bq, nullptr, Qp, MROWS, BDIM, BDIM, MODE_SPLIT);
    sgemm_kernel<<<gD, blk>>>(y, Wk, bk, nullptr, Kp, MROWS, BDIM, BDIM, MODE_SPLIT);
    sgemm_kernel<<<gD, blk>>>(y, Wv, bv, nullptr, Vp, MROWS, BDIM, BDIM, MODE_SPLIT);

    // fused attention -> [B,S,D]
    size_t shm = (size_t)(4 * 64 * AST) * sizeof(float) + 64 * sizeof(int);
    cudaFuncSetAttribute(attn_kernel, cudaFuncAttributeMaxDynamicSharedMemorySize, (int)shm);
    attn_kernel<<<dim3(SEQ / 64, NH, NB), blk, shm>>>(Qp, Kp, Vp, mask, attp);

    // s1 = x + attn @ Wo + bo ; x1 = LN(s1)
    sgemm_kernel<<<gD, blk>>>(attp, Wo, bo, x, s1p, MROWS, BDIM, BDIM, MODE_RES);
    ln_kernel<<<MROWS, blk>>>(s1p, g1, be1, x1p);

    // FFN: h = relu(x1 @ W1 + b1); s2 = x1 + h @ W2 + b2; out = LN(s2)
    sgemm_kernel<<<gH, blk>>>(x1p, W1, b1, nullptr, hp, MROWS, HIDN, BDIM, MODE_RELU);
    sgemm_kernel<<<gD, blk>>>(hp, W2, b2, x1p, s2p, MROWS, BDIM, HIDN, MODE_RES);
    ln_kernel<<<MROWS, blk>>>(s2p, g2, be2, out);
}